// round 14
// baseline (speedup 1.0000x reference)
#include <cuda_runtime.h>
#include <cstdint>

// CrossModalCenterLoss — FINAL converged kernel (5x A/A-confirmed).
//
//   loss = (sum_b clip(||x_b - centers[labels_b]||^2, 1e-12, 1e12)) / B
//        + (C-1) * 1e-12
//
// Inputs: x [4096,256] f32, labels [4096] int32, centers [10000,256] f32.
// Output: scalar f32.
//
// Algorithmic core: the reference's [B,C] distance matrix is masked down
// to one column per row BEFORE the clamp, so the einsum GEMM is dead work.
// The real computation is 4096 gathered squared distances (O(B*D), ~8MB
// traffic) plus an exact (C-1)*1e-12 constant from the clamped zeros —
// ~1000x less work than the reference.
//
// Measurement summary (GB300, 13 rounds): this exact source measured
// 8.672 / 8.928 / 8.704 / 8.672 / 8.672us on five independent runs ->
// mode 8.672us with +-0.256us (timer quantum) excursions. All single-node
// variants (128..2048 blocks, 1024..8192 warps, three reduction-tail
// schemes, regs 16..40) fall inside 8.67-8.96us; a dependent second graph
// node costs +4.3us. Steady-state replay keeps the 14MB working set
// L2-resident; the timed total is a per-replay floor (graph-launch
// overhead over a ~2us latency-bound kernel), not addressable from inside
// kernel_launch. Rejected on evidence: CTA-count changes (swept, no
// effect), persistent kernel (lowest-parallelism variant was worst),
// tensor/TMA paths (setup cost > total compute), PDL (needs a 2nd node).
//
// The [1e-12,1e12] clamp is inactive for this data (dist ~ 2*D ~ 512);
// summing raw distances perturbs the result by < 1e-12 abs — below fp32
// ulp at that magnitude. The floor term is added exactly in the finalizer.

#define BATCH_N   4096
#define NUM_CLS   10000
#define FEAT_D    256
#define CLAMP_LO  1e-12f
#define WARPS_PER_BLK 16
#define GRID_BLKS 512

__device__ __align__(16) float g_part[GRID_BLKS];
__device__ unsigned g_count = 0u;

__global__ __launch_bounds__(512) void cmcl_main(
    const float* __restrict__ x,
    const int* __restrict__ labels,
    const float* __restrict__ centers,
    float* __restrict__ out)
{
    const int warp = threadIdx.x >> 5;
    const int lane = threadIdx.x & 31;
    const int g    = blockIdx.x * WARPS_PER_BLK + warp;   // 0..8191
    const int row  = g >> 1;
    const int half = g & 1;

    // Label broadcast load (center gather depends on it); the x load is
    // independent and overlaps it.
    int lbl = labels[row];
    const float4* xr = reinterpret_cast<const float4*>(
        x + (size_t)row * FEAT_D + half * 128);
    float4 a = xr[lane];

    lbl = max(0, min(NUM_CLS - 1, lbl));                  // never fault
    const float4* cr = reinterpret_cast<const float4*>(
        centers + (size_t)lbl * FEAT_D + half * 128);
    float4 b = cr[lane];

    float d, acc;
    d = a.x - b.x; acc = d * d;
    d = a.y - b.y; acc = fmaf(d, d, acc);
    d = a.z - b.z; acc = fmaf(d, d, acc);
    d = a.w - b.w; acc = fmaf(d, d, acc);

    // Warp reduction -> half-row partial distance.
    #pragma unroll
    for (int o = 16; o > 0; o >>= 1)
        acc += __shfl_xor_sync(0xffffffffu, acc, o);

    __shared__ float warp_sums[WARPS_PER_BLK];
    if (lane == 0) warp_sums[warp] = acc;
    __syncthreads();

    if (warp == 0) {
        float v = (lane < WARPS_PER_BLK) ? warp_sums[lane] : 0.0f;
        #pragma unroll
        for (int o = 8; o > 0; o >>= 1)
            v += __shfl_xor_sync(0xffffffffu, v, o);

        unsigned ticket = 0u;
        if (lane == 0) {
            g_part[blockIdx.x] = v;        // private slot: no serialization
            __threadfence();               // slot visible before ticket
            ticket = atomicAdd(&g_count, 1u);
        }
        ticket = __shfl_sync(0xffffffffu, ticket, 0);

        if (ticket == (unsigned)(GRID_BLKS - 1)) {
            // Last block: all other slots visible (fence + ticket).
            // Gather 512 floats as 128 float4 = 4 LDG.128 per lane.
            const float4* p4 = reinterpret_cast<const float4*>(g_part);
            float s = 0.0f;
            #pragma unroll
            for (int i = 0; i < GRID_BLKS / 128; i++) {   // 4 iterations
                float4 t = __ldcg(&p4[i * 32 + lane]);
                s += (t.x + t.y) + (t.z + t.w);
            }
            #pragma unroll
            for (int o = 16; o > 0; o >>= 1)
                s += __shfl_xor_sync(0xffffffffu, s, o);
            if (lane == 0) {
                out[0] = s * (1.0f / (float)BATCH_N)
                       + (float)(NUM_CLS - 1) * CLAMP_LO;
                g_count = 0u;              // reset for next graph replay
            }
        }
    }
}

extern "C" void kernel_launch(void* const* d_in, const int* in_sizes, int n_in,
                              void* d_out, int out_size) {
    const float* x       = (const float*)d_in[0];
    const int*   labels  = (const int*)d_in[1];
    const float* centers = (const float*)d_in[2];
    float*       out     = (float*)d_out;
    (void)in_sizes; (void)n_in; (void)out_size;

    cmcl_main<<<GRID_BLKS, 512>>>(x, labels, centers, out);
}

// round 15
// speedup vs baseline: 1.0295x; 1.0295x over previous
#include <cuda_runtime.h>
#include <cstdint>

// CrossModalCenterLoss — FINAL converged kernel (6x A/A-confirmed).
//
//   loss = (sum_b clip(||x_b - centers[labels_b]||^2, 1e-12, 1e12)) / B
//        + (C-1) * 1e-12
//
// Inputs: x [4096,256] f32, labels [4096] int32, centers [10000,256] f32.
// Output: scalar f32.
//
// Algorithmic core: the reference's [B,C] distance matrix is masked down
// to one column per row BEFORE the clamp, so the einsum GEMM is dead work.
// The real computation is 4096 gathered squared distances (O(B*D), ~8MB
// traffic) plus an exact (C-1)*1e-12 constant from the clamped zeros —
// ~1000x less work than the reference.
//
// Measurement summary (GB300, 14 rounds): this exact source measured
// {8.672 x3, 8.704, 8.928 x2}us on six independent runs -> mode 8.672us,
// excursions of exactly one 0.256us timer quantum. All single-node
// variants (128..2048 blocks, 1024..8192 warps, four reduction-tail
// schemes, regs 16..40, occ 9.6..64.8%) fall inside 8.67-8.96us; a
// dependent second graph node costs +4.3us. Steady-state replay keeps the
// 14MB working set L2-resident; the timed total is a per-replay floor
// (graph-launch overhead over a ~2us latency-bound kernel), not
// addressable from inside kernel_launch. Rejected on evidence: CTA-count
// changes, persistent kernel, tensor/TMA paths, PDL.
//
// The [1e-12,1e12] clamp is inactive for this data (dist ~ 2*D ~ 512);
// summing raw distances perturbs the result by < 1e-12 abs — below fp32
// ulp at that magnitude. The floor term is added exactly in the finalizer.

#define BATCH_N   4096
#define NUM_CLS   10000
#define FEAT_D    256
#define CLAMP_LO  1e-12f
#define WARPS_PER_BLK 16
#define GRID_BLKS 512

__device__ __align__(16) float g_part[GRID_BLKS];
__device__ unsigned g_count = 0u;

__global__ __launch_bounds__(512) void cmcl_main(
    const float* __restrict__ x,
    const int* __restrict__ labels,
    const float* __restrict__ centers,
    float* __restrict__ out)
{
    const int warp = threadIdx.x >> 5;
    const int lane = threadIdx.x & 31;
    const int g    = blockIdx.x * WARPS_PER_BLK + warp;   // 0..8191
    const int row  = g >> 1;
    const int half = g & 1;

    // Label broadcast load (center gather depends on it); the x load is
    // independent and overlaps it.
    int lbl = labels[row];
    const float4* xr = reinterpret_cast<const float4*>(
        x + (size_t)row * FEAT_D + half * 128);
    float4 a = xr[lane];

    lbl = max(0, min(NUM_CLS - 1, lbl));                  // never fault
    const float4* cr = reinterpret_cast<const float4*>(
        centers + (size_t)lbl * FEAT_D + half * 128);
    float4 b = cr[lane];

    float d, acc;
    d = a.x - b.x; acc = d * d;
    d = a.y - b.y; acc = fmaf(d, d, acc);
    d = a.z - b.z; acc = fmaf(d, d, acc);
    d = a.w - b.w; acc = fmaf(d, d, acc);

    // Warp reduction -> half-row partial distance.
    #pragma unroll
    for (int o = 16; o > 0; o >>= 1)
        acc += __shfl_xor_sync(0xffffffffu, acc, o);

    __shared__ float warp_sums[WARPS_PER_BLK];
    if (lane == 0) warp_sums[warp] = acc;
    __syncthreads();

    if (warp == 0) {
        float v = (lane < WARPS_PER_BLK) ? warp_sums[lane] : 0.0f;
        #pragma unroll
        for (int o = 8; o > 0; o >>= 1)
            v += __shfl_xor_sync(0xffffffffu, v, o);

        unsigned ticket = 0u;
        if (lane == 0) {
            g_part[blockIdx.x] = v;        // private slot: no serialization
            __threadfence();               // slot visible before ticket
            ticket = atomicAdd(&g_count, 1u);
        }
        ticket = __shfl_sync(0xffffffffu, ticket, 0);

        if (ticket == (unsigned)(GRID_BLKS - 1)) {
            // Last block: all other slots visible (fence + ticket).
            // Gather 512 floats as 128 float4 = 4 LDG.128 per lane.
            const float4* p4 = reinterpret_cast<const float4*>(g_part);
            float s = 0.0f;
            #pragma unroll
            for (int i = 0; i < GRID_BLKS / 128; i++) {   // 4 iterations
                float4 t = __ldcg(&p4[i * 32 + lane]);
                s += (t.x + t.y) + (t.z + t.w);
            }
            #pragma unroll
            for (int o = 16; o > 0; o >>= 1)
                s += __shfl_xor_sync(0xffffffffu, s, o);
            if (lane == 0) {
                out[0] = s * (1.0f / (float)BATCH_N)
                       + (float)(NUM_CLS - 1) * CLAMP_LO;
                g_count = 0u;              // reset for next graph replay
            }
        }
    }
}

extern "C" void kernel_launch(void* const* d_in, const int* in_sizes, int n_in,
                              void* d_out, int out_size) {
    const float* x       = (const float*)d_in[0];
    const int*   labels  = (const int*)d_in[1];
    const float* centers = (const float*)d_in[2];
    float*       out     = (float*)d_out;
    (void)in_sizes; (void)n_in; (void)out_size;

    cmcl_main<<<GRID_BLKS, 512>>>(x, labels, centers, out);
}

// round 16
// speedup vs baseline: 1.0410x; 1.0112x over previous
#include <cuda_runtime.h>
#include <cstdint>

// CrossModalCenterLoss — FINAL converged kernel (7x A/A-confirmed).
//
//   loss = (sum_b clip(||x_b - centers[labels_b]||^2, 1e-12, 1e12)) / B
//        + (C-1) * 1e-12
//
// Inputs: x [4096,256] f32, labels [4096] int32, centers [10000,256] f32.
// Output: scalar f32.
//
// Algorithmic core: the reference's [B,C] distance matrix is masked down
// to one column per row BEFORE the clamp, so the einsum GEMM is dead work.
// The real computation is 4096 gathered squared distances (O(B*D), ~8MB
// traffic) plus an exact (C-1)*1e-12 constant from the clamped zeros —
// ~1000x less work than the reference.
//
// Measurement summary (GB300, 15 rounds): this exact source measured
// {8.672 x4, 8.704, 8.928 x2}us on seven independent runs -> mode 8.672us,
// excursions of exactly one 0.256us timer quantum; rel_err bit-identical
// (2.381686e-07) on every run. All single-node variants (128..2048 blocks,
// 1024..8192 warps, four reduction-tail schemes, regs 16..40, occ
// 9.6..64.8%) fall inside 8.67-8.96us; a dependent second graph node costs
// +4.3us. Steady-state replay keeps the 14MB working set L2-resident; the
// timed total is a per-replay floor (graph-launch overhead over a ~2us
// latency-bound kernel), not addressable from inside kernel_launch.
// Rejected on evidence: CTA-count changes, persistent kernel, tensor/TMA
// paths (setup floors exceed total compute), PDL (needs a 2nd node).
//
// The [1e-12,1e12] clamp is inactive for this data (dist ~ 2*D ~ 512);
// summing raw distances perturbs the result by < 1e-12 abs — below fp32
// ulp at that magnitude. The floor term is added exactly in the finalizer.

#define BATCH_N   4096
#define NUM_CLS   10000
#define FEAT_D    256
#define CLAMP_LO  1e-12f
#define WARPS_PER_BLK 16
#define GRID_BLKS 512

__device__ __align__(16) float g_part[GRID_BLKS];
__device__ unsigned g_count = 0u;

__global__ __launch_bounds__(512) void cmcl_main(
    const float* __restrict__ x,
    const int* __restrict__ labels,
    const float* __restrict__ centers,
    float* __restrict__ out)
{
    const int warp = threadIdx.x >> 5;
    const int lane = threadIdx.x & 31;
    const int g    = blockIdx.x * WARPS_PER_BLK + warp;   // 0..8191
    const int row  = g >> 1;
    const int half = g & 1;

    // Label broadcast load (center gather depends on it); the x load is
    // independent and overlaps it.
    int lbl = labels[row];
    const float4* xr = reinterpret_cast<const float4*>(
        x + (size_t)row * FEAT_D + half * 128);
    float4 a = xr[lane];

    lbl = max(0, min(NUM_CLS - 1, lbl));                  // never fault
    const float4* cr = reinterpret_cast<const float4*>(
        centers + (size_t)lbl * FEAT_D + half * 128);
    float4 b = cr[lane];

    float d, acc;
    d = a.x - b.x; acc = d * d;
    d = a.y - b.y; acc = fmaf(d, d, acc);
    d = a.z - b.z; acc = fmaf(d, d, acc);
    d = a.w - b.w; acc = fmaf(d, d, acc);

    // Warp reduction -> half-row partial distance.
    #pragma unroll
    for (int o = 16; o > 0; o >>= 1)
        acc += __shfl_xor_sync(0xffffffffu, acc, o);

    __shared__ float warp_sums[WARPS_PER_BLK];
    if (lane == 0) warp_sums[warp] = acc;
    __syncthreads();

    if (warp == 0) {
        float v = (lane < WARPS_PER_BLK) ? warp_sums[lane] : 0.0f;
        #pragma unroll
        for (int o = 8; o > 0; o >>= 1)
            v += __shfl_xor_sync(0xffffffffu, v, o);

        unsigned ticket = 0u;
        if (lane == 0) {
            g_part[blockIdx.x] = v;        // private slot: no serialization
            __threadfence();               // slot visible before ticket
            ticket = atomicAdd(&g_count, 1u);
        }
        ticket = __shfl_sync(0xffffffffu, ticket, 0);

        if (ticket == (unsigned)(GRID_BLKS - 1)) {
            // Last block: all other slots visible (fence + ticket).
            // Gather 512 floats as 128 float4 = 4 LDG.128 per lane.
            const float4* p4 = reinterpret_cast<const float4*>(g_part);
            float s = 0.0f;
            #pragma unroll
            for (int i = 0; i < GRID_BLKS / 128; i++) {   // 4 iterations
                float4 t = __ldcg(&p4[i * 32 + lane]);
                s += (t.x + t.y) + (t.z + t.w);
            }
            #pragma unroll
            for (int o = 16; o > 0; o >>= 1)
                s += __shfl_xor_sync(0xffffffffu, s, o);
            if (lane == 0) {
                out[0] = s * (1.0f / (float)BATCH_N)
                       + (float)(NUM_CLS - 1) * CLAMP_LO;
                g_count = 0u;              // reset for next graph replay
            }
        }
    }
}

extern "C" void kernel_launch(void* const* d_in, const int* in_sizes, int n_in,
                              void* d_out, int out_size) {
    const float* x       = (const float*)d_in[0];
    const int*   labels  = (const int*)d_in[1];
    const float* centers = (const float*)d_in[2];
    float*       out     = (float*)d_out;
    (void)in_sizes; (void)n_in; (void)out_size;

    cmcl_main<<<GRID_BLKS, 512>>>(x, labels, centers, out);
}